// round 3
// baseline (speedup 1.0000x reference)
#include <cuda_runtime.h>
#include <cuda_bf16.h>

// Sliding-window unfold: out[b, i, j] = x[b, i + j]
//   x:   [B=128, L=8192]  float32
//   out: [B=128, NWIN=8162, W=31] float32
//
// R3: smem-staged. Block = 1024 consecutive flat outputs; their source window
// spans <= 64 input floats, staged once in shared memory (80 scalar LDG per
// BLOCK instead of 4096). Hot path per thread: 4x LDS + 1x STG.128.
// Straddling / tail blocks (~128 of 31628) use the direct-LDG fallback.

static constexpr unsigned Bv    = 128u;
static constexpr unsigned Lv    = 8192u;
static constexpr unsigned Wv    = 31u;
static constexpr unsigned Rv    = Wv / 2u;           // 15
static constexpr unsigned NWIN  = Lv - 2u * Rv;      // 8162
static constexpr unsigned ROW   = NWIN * Wv;         // 253022
static constexpr unsigned TOTAL = Bv * ROW;          // 32,386,816
static constexpr unsigned OUTS_PER_BLOCK = 1024u;    // 256 thr x 4
static constexpr unsigned NBLOCKS = (TOTAL + OUTS_PER_BLOCK - 1u) / OUTS_PER_BLOCK; // 31628

__global__ void __launch_bounds__(256)
WindowAlignmentLayer_65876208386448_kernel(const float* __restrict__ x,
                                           float* __restrict__ out) {
    __shared__ float sx[80];

    const unsigned t  = threadIdx.x;
    const unsigned o0 = blockIdx.x * OUTS_PER_BLOCK;   // block's first flat output

    const unsigned b0   = o0 / ROW;                    // magic-multiply
    const unsigned rem0 = o0 - b0 * ROW;

    // Fast path requires: whole block inside one batch row, and full block.
    const bool fast = (rem0 + OUTS_PER_BLOCK <= ROW) && (o0 + OUTS_PER_BLOCK <= TOTAL);

    if (fast) {
        const unsigned i0 = rem0 / Wv;                 // first window index in block
        const float* __restrict__ xrow = x + (size_t)b0 * Lv;

        // Stage source span: src in [i0, i0+63]; 80 floats with clamp padding.
        if (t < 80u) {
            unsigned g = i0 + t;
            sx[t] = xrow[g < Lv ? g : (Lv - 1u)];
        }
        __syncthreads();

        const unsigned rem = rem0 + t * 4u;
        const unsigned i   = rem / Wv;                 // magic-multiply
        const unsigned j   = rem - i * Wv;
        const unsigned s   = i + j - i0;               // local src base, <= 61

        float4 o4;
        {
            float v[4];
#pragma unroll
            for (int k = 0; k < 4; ++k) {
                unsigned jk  = j + (unsigned)k;
                unsigned src = s + (unsigned)k - (jk >= Wv ? (Wv - 1u) : 0u);
                v[k] = sx[src];
            }
            o4.x = v[0]; o4.y = v[1]; o4.z = v[2]; o4.w = v[3];
        }
        *reinterpret_cast<float4*>(out + (o0 + t * 4u)) = o4;
        return;
    }

    // ---- Cold path: block straddles a batch row, or is the partial tail. ----
    const unsigned o = o0 + t * 4u;
    if (o >= TOTAL) return;                            // tail guard (TOTAL % 4 == 0)

    const unsigned b   = o / ROW;
    const unsigned rem = o - b * ROW;
    const unsigned i   = rem / Wv;
    const unsigned j   = rem - i * Wv;
    const float* __restrict__ xrow = x + (size_t)b * Lv;

    float v[4];
#pragma unroll
    for (int k = 0; k < 4; ++k) {
        unsigned rk = rem + (unsigned)k;
        const float* __restrict__ xr = xrow;
        unsigned src;
        if (rk >= ROW) {                               // spills into next batch
            xr  = xrow + Lv;
            src = rk - ROW;                            // < 4 -> i'=0, j'=src
        } else {
            unsigned jk = j + (unsigned)k;
            src = i + jk - (jk >= Wv ? (Wv - 1u) : 0u);
        }
        v[k] = __ldg(xr + src);
    }
    float4 o4;
    o4.x = v[0]; o4.y = v[1]; o4.z = v[2]; o4.w = v[3];
    *reinterpret_cast<float4*>(out + o) = o4;
}

extern "C" void kernel_launch(void* const* d_in, const int* in_sizes, int n_in,
                              void* d_out, int out_size) {
    (void)in_sizes; (void)n_in; (void)out_size;
    const float* x   = (const float*)d_in[0];
    float*       out = (float*)d_out;

    WindowAlignmentLayer_65876208386448_kernel<<<NBLOCKS, 256>>>(x, out);
}